// round 12
// baseline (speedup 1.0000x reference)
#include <cuda_runtime.h>

// out[m][n] = C[m][n] * D[n];  8192 x 8192 f32, row-major.
// Final lever test: 8-deep batching x write-through stores.
// 8192 blocks x 256 threads x 8 float4 = 16,777,216 float4s (single pass).
// 8 front-batched loads (MLP=8), then 8 consecutive __stwt stores: WT bypasses
// L2 write buffering, so consecutive same-thread WT stores form long
// same-direction bursts at the DRAM controllers.
// STRIDE = 8192*256 = 2,097,152 (32 MB), multiple of NR4=2048 -> the D scale
// is invariant across all 8 elements, loaded once per thread.

static constexpr int NR4    = 2048;          // float4s per row
static constexpr int STRIDE = 8192 * 256;    // 2,097,152

__global__ __launch_bounds__(256)
void colscale_kernel(const float4* __restrict__ C,
                     const float4* __restrict__ D,
                     float4* __restrict__ out)
{
    const int i = blockIdx.x * 256 + threadIdx.x;   // 0 .. 2,097,151

    const float4 d = __ldg(&D[i & (NR4 - 1)]);

    float4 c[8];
    #pragma unroll
    for (int k = 0; k < 8; k++)
        c[k] = C[i + k * STRIDE];

    #pragma unroll
    for (int k = 0; k < 8; k++) {
        c[k].x *= d.x; c[k].y *= d.y; c[k].z *= d.z; c[k].w *= d.w;
    }

    #pragma unroll
    for (int k = 0; k < 8; k++)
        __stwt(&out[i + k * STRIDE], c[k]);
}

extern "C" void kernel_launch(void* const* d_in, const int* in_sizes, int n_in,
                              void* d_out, int out_size)
{
    const float4* C = (const float4*)d_in[0];
    const float4* D = (const float4*)d_in[1];
    float4* out     = (float4*)d_out;

    colscale_kernel<<<8192, 256>>>(C, D, out);
}

// round 13
// speedup vs baseline: 1.0148x; 1.0148x over previous
#include <cuda_runtime.h>

// FINAL (R11, best measured: 81.9 us harness / 74.8 us kernel, 6.52 TB/s).
// out[m][n] = C[m][n] * D[n];  8192 x 8192 f32, row-major.
//
// Structure: single pass, 16384 blocks x 256 threads x 4 float4. The 4
// per-thread accesses are spaced STRIDE = 64 MB apart, spreading concurrent
// requests across all HBM channels / both L2 dies. STRIDE % NR4 == 0, so each
// thread's column index is invariant -> D loaded exactly once per thread.
// Stores are write-through (__stwt): delivered to the controllers in issue
// order, the only store policy that never measured worse than default.
//
// Session conclusion: 11 variants (occupancy 47-84%, MLP 4-8, 128/256-bit,
// batch 4/8, persistent grid, all cache policies) all land at 6.3-6.6 TB/s —
// the kernel is pinned at the mixed read+write HBM ceiling (~82% of spec)
// with compute/issue fully slack. Traffic (512 MB) is irreducible.

static constexpr int NR4    = 2048;                 // float4s per row
static constexpr int STRIDE = 16384 * 256;          // grid * block = 4,194,304

__global__ __launch_bounds__(256, 6)
void colscale_kernel(const float4* __restrict__ C,
                     const float4* __restrict__ D,
                     float4* __restrict__ out)
{
    const int i = blockIdx.x * 256 + threadIdx.x;   // 0 .. 4,194,303

    // STRIDE is a multiple of NR4, so column index is invariant across the 4.
    const float4 d = __ldg(&D[i & (NR4 - 1)]);

    const int i0 = i;
    const int i1 = i + STRIDE;
    const int i2 = i + 2 * STRIDE;
    const int i3 = i + 3 * STRIDE;

    // Front-batched loads (MLP=4), 64 MB apart.
    float4 c0 = C[i0];
    float4 c1 = C[i1];
    float4 c2 = C[i2];
    float4 c3 = C[i3];

    c0.x *= d.x; c0.y *= d.y; c0.z *= d.z; c0.w *= d.w;
    c1.x *= d.x; c1.y *= d.y; c1.z *= d.z; c1.w *= d.w;
    c2.x *= d.x; c2.y *= d.y; c2.z *= d.z; c2.w *= d.w;
    c3.x *= d.x; c3.y *= d.y; c3.z *= d.z; c3.w *= d.w;

    __stwt(&out[i0], c0);
    __stwt(&out[i1], c1);
    __stwt(&out[i2], c2);
    __stwt(&out[i3], c3);
}

extern "C" void kernel_launch(void* const* d_in, const int* in_sizes, int n_in,
                              void* d_out, int out_size)
{
    const float4* C = (const float4*)d_in[0];
    const float4* D = (const float4*)d_in[1];
    float4* out     = (float4*)d_out;

    colscale_kernel<<<16384, 256>>>(C, D, out);
}

// round 14
// speedup vs baseline: 1.0156x; 1.0008x over previous
#include <cuda_runtime.h>

// out[m][n] = C[m][n] * D[n];  8192 x 8192 f32, row-major.
// R11 structure with ONE isolated change: block=512 (grid=8192), keeping the
// global stride identical (8192*512 = 16384*256 = 4,194,304 float4s = 64 MB),
// so the thread->address map is unchanged; only the CTA partitioning of that
// map changes (placement granularity + L1tex queue sharing).
// D loaded once per thread (STRIDE % NR4 == 0); write-through stores (R11).

static constexpr int NR4    = 2048;                 // float4s per row
static constexpr int STRIDE = 8192 * 512;           // 4,194,304 (same as R11)

__global__ __launch_bounds__(512, 3)
void colscale_kernel(const float4* __restrict__ C,
                     const float4* __restrict__ D,
                     float4* __restrict__ out)
{
    const int i = blockIdx.x * 512 + threadIdx.x;   // 0 .. 4,194,303

    // STRIDE is a multiple of NR4, so column index is invariant across the 4.
    const float4 d = __ldg(&D[i & (NR4 - 1)]);

    const int i0 = i;
    const int i1 = i + STRIDE;
    const int i2 = i + 2 * STRIDE;
    const int i3 = i + 3 * STRIDE;

    // Front-batched loads (MLP=4), 64 MB apart.
    float4 c0 = C[i0];
    float4 c1 = C[i1];
    float4 c2 = C[i2];
    float4 c3 = C[i3];

    c0.x *= d.x; c0.y *= d.y; c0.z *= d.z; c0.w *= d.w;
    c1.x *= d.x; c1.y *= d.y; c1.z *= d.z; c1.w *= d.w;
    c2.x *= d.x; c2.y *= d.y; c2.z *= d.z; c2.w *= d.w;
    c3.x *= d.x; c3.y *= d.y; c3.z *= d.z; c3.w *= d.w;

    __stwt(&out[i0], c0);
    __stwt(&out[i1], c1);
    __stwt(&out[i2], c2);
    __stwt(&out[i3], c3);
}

extern "C" void kernel_launch(void* const* d_in, const int* in_sizes, int n_in,
                              void* d_out, int out_size)
{
    const float4* C = (const float4*)d_in[0];
    const float4* D = (const float4*)d_in[1];
    float4* out     = (float4*)d_out;

    colscale_kernel<<<8192, 512>>>(C, D, out);
}